// round 15
// baseline (speedup 1.0000x reference)
#include <cuda_runtime.h>
#include <cuda_fp16.h>

#define NMAX   100000
#define EMAX   1600000
#define DIN    64
#define NHEAD  4
#define HDIM   16
#define FEAT   64   // NHEAD*HDIM
#define ROW    80   // augmented output width: 64 h + 4 as + 4 ad + u + v + 6 pad
#define SCAN_B 1024

// -------- scratch (static device globals; no allocations allowed) ----------
__device__ __align__(16) static __half g_h[(size_t)NMAX * FEAT];  // fp16 node features
__device__ __align__(16) static float2 g_uas[NMAX * NHEAD];  // (u, as_head)
__device__ __align__(16) static float2 g_vad[NMAX * NHEAD];  // (v+off, ad_head+ba)

__device__ __align__(16) static float g_Wp[DIN * ROW];  // augmented weights
__device__ __align__(16) static float g_bp[ROW];        // augmented bias

// deg + publish-flags share one memset region
__device__ static int g_degfv[NMAX + 256];
__device__ static int g_cursor[NMAX];
__device__ static int g_offs[NMAX + 1];
__device__ static int g_srcs[EMAX];

// ---------------------------------------------------------------------------
// 1) Build the augmented weight matrix W' (64x80) + bias b'(80).
//    cols 0..63 = Wl; 64+h = Wl_head @ Wa_src; 68+h = Wl_head @ Wa_dst;
//    72 = cu = Wd@(Wf0+Wf2); 73 = cv = Wd@(Wf1-Wf2); 74..79 = 0.
//    b': 0..63 = bl; 64+h = bl_head.Wa_s; 68+h = bl_head.Wa_d + ba;
//    72 = 0; 73 = off; 74..79 = 0.
// ---------------------------------------------------------------------------
__global__ void __launch_bounds__(512)
precompute_kernel(const float* __restrict__ Wl, const float* __restrict__ bl,
                  const float* __restrict__ Wa, const float* __restrict__ ba,
                  const float* __restrict__ Wd, const float* __restrict__ bd,
                  const float* __restrict__ Wf, const float* __restrict__ bf) {
    __shared__ float wfu[DIN], wfv[DIN], s_wa[2 * HDIM], s_bl[FEAT];
    int tid = threadIdx.x;
    if (tid < DIN) {
        float f0 = Wf[tid], f1 = Wf[DIN + tid], f2 = Wf[2 * DIN + tid];
        wfu[tid] = f0 + f2;
        wfv[tid] = f1 - f2;
        s_bl[tid] = bl[tid];
    }
    if (tid < 2 * HDIM) s_wa[tid] = Wa[tid];
    __syncthreads();

    int j = tid >> 3;      // row 0..63
    int p = tid & 7;
    const float* wlrow = Wl + j * DIN;

    // copy cols p*8 .. p*8+7
#pragma unroll
    for (int k = 0; k < 8; k++)
        g_Wp[j * ROW + p * 8 + k] = wlrow[p * 8 + k];

    // folded attention columns
    if (p < 4) {
        float a = 0.f;
#pragma unroll
        for (int k = 0; k < HDIM; k++) a += wlrow[p * HDIM + k] * s_wa[k];
        g_Wp[j * ROW + 64 + p] = a;
    } else {
        int h = p - 4;
        float a = 0.f;
#pragma unroll
        for (int k = 0; k < HDIM; k++) a += wlrow[h * HDIM + k] * s_wa[HDIM + k];
        g_Wp[j * ROW + 68 + h] = a;
    }
    // cu / cv / pads
    if (p == 0) {
        float cu = 0.f;
#pragma unroll 8
        for (int jj = 0; jj < DIN; jj++) cu += Wd[j * DIN + jj] * wfu[jj];
        g_Wp[j * ROW + 72] = cu;
    }
    if (p == 1) {
        float cv = 0.f;
#pragma unroll 8
        for (int jj = 0; jj < DIN; jj++) cv += Wd[j * DIN + jj] * wfv[jj];
        g_Wp[j * ROW + 73] = cv;
    }
    if (p == 2) { g_Wp[j*ROW+74]=0.f; g_Wp[j*ROW+75]=0.f; g_Wp[j*ROW+76]=0.f; }
    if (p == 3) { g_Wp[j*ROW+77]=0.f; g_Wp[j*ROW+78]=0.f; g_Wp[j*ROW+79]=0.f; }

    // biases (threads 64..143 handle cols 0..79 -> reuse tids 64..143)
    int c = tid - 64;
    if (c >= 0 && c < ROW) {
        float b = 0.f;
        if (c < 64) b = s_bl[c];
        else if (c < 68) {
            int h = c - 64;
#pragma unroll
            for (int k = 0; k < HDIM; k++) b += s_bl[h * HDIM + k] * s_wa[k];
        } else if (c < 72) {
            int h = c - 68;
#pragma unroll
            for (int k = 0; k < HDIM; k++) b += s_bl[h * HDIM + k] * s_wa[HDIM + k];
            b += ba[0];
        } else if (c == 73) {
            b = bf[0];
            for (int k = 0; k < DIN; k++) b += bd[k] * (wfu[k] + wfv[k]);
        }
        g_bp[c] = b;
    }
}

// ---------------------------------------------------------------------------
// 2) Degree histogram over dst, 4 edges/thread (deg zeroed by memsetAsync).
// ---------------------------------------------------------------------------
__global__ void hist_kernel(const int* __restrict__ dst, int E) {
    int q = blockIdx.x * blockDim.x + threadIdx.x;
    int e = q * 4;
    if (e + 3 < E) {
        int4 d4 = *reinterpret_cast<const int4*>(dst + e);
        atomicAdd(&g_degfv[d4.x], 1);
        atomicAdd(&g_degfv[d4.y], 1);
        atomicAdd(&g_degfv[d4.z], 1);
        atomicAdd(&g_degfv[d4.w], 1);
    } else {
        for (int k = e; k < E; k++) atomicAdd(&g_degfv[dst[k]], 1);
    }
}

// ---------------------------------------------------------------------------
// 3) Single-pass exclusive scan (98 co-resident blocks, aggregate lookback).
// ---------------------------------------------------------------------------
__global__ void scan_onepass_kernel(int N, int NB) {
    __shared__ int sm[SCAN_B];
    __shared__ int s_base;
    int b = blockIdx.x;
    int tid = threadIdx.x;
    int idx = b * SCAN_B + tid;

    int v = (idx < N) ? g_degfv[idx] : 0;
    sm[tid] = v;
    __syncthreads();
#pragma unroll
    for (int o = 1; o < SCAN_B; o <<= 1) {
        int tmp = (tid >= o) ? sm[tid - o] : 0;
        __syncthreads();
        sm[tid] += tmp;
        __syncthreads();
    }
    int incl = sm[tid];
    int agg = sm[SCAN_B - 1];

    if (tid == 0) {
        __threadfence();
        atomicExch(&g_degfv[NMAX + b], agg + 1);
    }
    if (tid < 32) {
        int contrib = 0;
        for (int t = tid; t < b; t += 32) {
            int fv;
            do { fv = atomicAdd(&g_degfv[NMAX + t], 0); } while (fv == 0);
            contrib += fv - 1;
        }
#pragma unroll
        for (int o = 16; o > 0; o >>= 1)
            contrib += __shfl_down_sync(0xffffffffu, contrib, o);
        if (tid == 0) s_base = contrib;
    }
    __syncthreads();
    int base = s_base;

    if (idx < N) {
        int off = base + incl - v;
        g_offs[idx] = off;
        g_cursor[idx] = off;
    }
    if (b == NB - 1 && tid == 0) g_offs[N] = base + agg;
}

// ---------------------------------------------------------------------------
// 4) Scatter src ids into dst-sorted order, 4 edges/thread.
// ---------------------------------------------------------------------------
__global__ void scatter_kernel(const int* __restrict__ src,
                               const int* __restrict__ dst, int E) {
    int q = blockIdx.x * blockDim.x + threadIdx.x;
    int e = q * 4;
    if (e + 3 < E) {
        int4 s4 = *reinterpret_cast<const int4*>(src + e);
        int4 d4 = *reinterpret_cast<const int4*>(dst + e);
        g_srcs[atomicAdd(&g_cursor[d4.x], 1)] = s4.x;
        g_srcs[atomicAdd(&g_cursor[d4.y], 1)] = s4.y;
        g_srcs[atomicAdd(&g_cursor[d4.z], 1)] = s4.z;
        g_srcs[atomicAdd(&g_cursor[d4.w], 1)] = s4.w;
    } else {
        for (int k = e; k < E; k++)
            g_srcs[atomicAdd(&g_cursor[dst[k]], 1)] = src[k];
    }
}

// ---------------------------------------------------------------------------
// 5) Node GEMM: x[N,64] @ W'[64,80]. Tile = 4 nodes x 20 cols per thread;
//    4 threads (a quad) cover one node group's 80 cols. Quad lanes load the
//    same x rows (warp broadcast). LDS per node: 1.28 KB (was 8 KB).
// ---------------------------------------------------------------------------
__global__ void __launch_bounds__(128)
node_kernel(const float* __restrict__ x, int N) {
    __shared__ __align__(16) float s_wp[DIN * ROW];   // 20480 B
    __shared__ __align__(16) float s_bp[ROW];

    int tid = threadIdx.x;
    {
        const float4* src4 = reinterpret_cast<const float4*>(g_Wp);
        float4* dst4 = reinterpret_cast<float4*>(s_wp);
        for (int i = tid; i < DIN * ROW / 4; i += 128) dst4[i] = src4[i];
        if (tid < ROW) s_bp[tid] = g_bp[tid];
    }
    __syncthreads();

    int quad = tid >> 2;     // 0..31
    int c = tid & 3;         // col group: cols [c*20, c*20+20)
    int nbase = blockIdx.x * 128 + quad * 4;
    if (nbase >= N) return;

    // accumulators: 4 nodes x 10 f32x2 (=20 floats), seeded with bias
    unsigned long long acc0[10], acc1[10], acc2[10], acc3[10];
    {
        const unsigned long long* bp =
            reinterpret_cast<const unsigned long long*>(&s_bp[c * 20]);
#pragma unroll
        for (int q = 0; q < 10; q++) {
            unsigned long long b = bp[q];
            acc0[q] = b; acc1[q] = b; acc2[q] = b; acc3[q] = b;
        }
    }

    int n0 = nbase;
    int n1 = min(nbase + 1, N - 1);
    int n2 = min(nbase + 2, N - 1);
    int n3 = min(nbase + 3, N - 1);
    const float4* xr0 = reinterpret_cast<const float4*>(x + (size_t)n0 * DIN);
    const float4* xr1 = reinterpret_cast<const float4*>(x + (size_t)n1 * DIN);
    const float4* xr2 = reinterpret_cast<const float4*>(x + (size_t)n2 * DIN);
    const float4* xr3 = reinterpret_cast<const float4*>(x + (size_t)n3 * DIN);

#pragma unroll 1
    for (int i4 = 0; i4 < DIN / 4; i4++) {
        float4 xa = xr0[i4], xb = xr1[i4], xc = xr2[i4], xd = xr3[i4];
        float xs0[4] = {xa.x, xa.y, xa.z, xa.w};
        float xs1[4] = {xb.x, xb.y, xb.z, xb.w};
        float xs2[4] = {xc.x, xc.y, xc.z, xc.w};
        float xs3[4] = {xd.x, xd.y, xd.z, xd.w};
#pragma unroll
        for (int j = 0; j < 4; j++) {
            int i = i4 * 4 + j;
            unsigned long long x0s, x1s, x2s, x3s;
            asm("mov.b64 %0, {%1, %1};" : "=l"(x0s) : "f"(xs0[j]));
            asm("mov.b64 %0, {%1, %1};" : "=l"(x1s) : "f"(xs1[j]));
            asm("mov.b64 %0, {%1, %1};" : "=l"(x2s) : "f"(xs2[j]));
            asm("mov.b64 %0, {%1, %1};" : "=l"(x3s) : "f"(xs3[j]));
            const ulonglong2* wrow =
                reinterpret_cast<const ulonglong2*>(&s_wp[i * ROW + c * 20]);
#pragma unroll
            for (int q = 0; q < 5; q++) {
                ulonglong2 wv = wrow[q];
                asm("fma.rn.f32x2 %0, %1, %2, %0;" : "+l"(acc0[q*2+0]) : "l"(wv.x), "l"(x0s));
                asm("fma.rn.f32x2 %0, %1, %2, %0;" : "+l"(acc0[q*2+1]) : "l"(wv.y), "l"(x0s));
                asm("fma.rn.f32x2 %0, %1, %2, %0;" : "+l"(acc1[q*2+0]) : "l"(wv.x), "l"(x1s));
                asm("fma.rn.f32x2 %0, %1, %2, %0;" : "+l"(acc1[q*2+1]) : "l"(wv.y), "l"(x1s));
                asm("fma.rn.f32x2 %0, %1, %2, %0;" : "+l"(acc2[q*2+0]) : "l"(wv.x), "l"(x2s));
                asm("fma.rn.f32x2 %0, %1, %2, %0;" : "+l"(acc2[q*2+1]) : "l"(wv.y), "l"(x2s));
                asm("fma.rn.f32x2 %0, %1, %2, %0;" : "+l"(acc3[q*2+0]) : "l"(wv.x), "l"(x3s));
                asm("fma.rn.f32x2 %0, %1, %2, %0;" : "+l"(acc3[q*2+1]) : "l"(wv.y), "l"(x3s));
            }
        }
    }

    // writeback
#pragma unroll
    for (int m = 0; m < 4; m++) {
        int n = nbase + m;
        if (n >= N) break;
        const unsigned long long* acc =
            (m == 0) ? acc0 : (m == 1) ? acc1 : (m == 2) ? acc2 : acc3;
        float val[20];
#pragma unroll
        for (int q = 0; q < 10; q++)
            asm("mov.b64 {%0, %1}, %2;"
                : "=f"(val[2 * q]), "=f"(val[2 * q + 1]) : "l"(acc[q]));

        if (c < 3) {
            // 20 h-feature columns starting at c*20 (even -> half2-aligned)
            __half2* hp = reinterpret_cast<__half2*>(&g_h[(size_t)n * FEAT + c * 20]);
#pragma unroll
            for (int q = 0; q < 10; q++)
                hp[q] = __floats2half2_rn(val[2 * q], val[2 * q + 1]);
        } else {
            // cols 60..63 = h features; 64..79 = scalars
            __half2* hp = reinterpret_cast<__half2*>(&g_h[(size_t)n * FEAT + 60]);
            hp[0] = __floats2half2_rn(val[0], val[1]);
            hp[1] = __floats2half2_rn(val[2], val[3]);
            float u = val[12];       // col 72
            float voff = val[13];    // col 73 (off folded via bias)
#pragma unroll
            for (int h = 0; h < NHEAD; h++) {
                g_uas[n * NHEAD + h] = make_float2(u, val[4 + h]);     // col 64+h
                g_vad[n * NHEAD + h] = make_float2(voff, val[8 + h]);  // col 68+h (+ba folded)
            }
        }
    }
}

// ---------------------------------------------------------------------------
// 6) CSR reduce: 4 threads per dst node. Lane t == head t (16 fp16 features,
//    two independent uint4 loads). No global-constant loads.
// ---------------------------------------------------------------------------
__global__ void __launch_bounds__(256)
reduce_kernel(float* __restrict__ out, int N) {
    int gid = blockIdx.x * blockDim.x + threadIdx.x;
    int n = gid >> 2;
    if (n >= N) return;
    int head = gid & 3;

    int beg = g_offs[n];
    int end = g_offs[n + 1];

    float2 vad = __ldg(&g_vad[n * NHEAD + head]);
    float vofs = vad.x;
    float adb  = vad.y;

    float acc[16];
#pragma unroll
    for (int k = 0; k < 16; k++) acc[k] = 0.f;
    float dsum = 0.f;

    if (beg < end) {
        int s = __ldg(&g_srcs[beg]);
        for (int p = beg; p < end; p++) {
            int s_next = (p + 1 < end) ? __ldg(&g_srcs[p + 1]) : 0;
            float2 ua = __ldg(&g_uas[s * NHEAD + head]);
            const uint4* hp = reinterpret_cast<const uint4*>(
                &g_h[(size_t)s * FEAT + head * HDIM]);
            uint4 raw0 = hp[0];
            uint4 raw1 = hp[1];

            float arg = ua.x + vofs;
            float sg = (arg > 0.f) ? 1.f : ((arg < 0.f) ? -1.f : 0.f);
            float al = sg * ua.y + adb;
            al = (al > 0.f) ? al : 0.01f * al;          // leaky_relu
            float w = __expf(al);
            float ws = w * sg;

            const __half2* c0 = reinterpret_cast<const __half2*>(&raw0);
            const __half2* c1 = reinterpret_cast<const __half2*>(&raw1);
#pragma unroll
            for (int q = 0; q < 4; q++) {
                float2 f0 = __half22float2(c0[q]);
                float2 f1 = __half22float2(c1[q]);
                acc[q * 2 + 0] += ws * f0.x;
                acc[q * 2 + 1] += ws * f0.y;
                acc[8 + q * 2 + 0] += ws * f1.x;
                acc[8 + q * 2 + 1] += ws * f1.y;
            }
            dsum += w;
            s = s_next;
        }
    }

    float inv = 1.f / fmaxf(dsum, 1e-16f);
    float* op = &out[(size_t)n * FEAT + head * HDIM];
#pragma unroll
    for (int q = 0; q < 4; q++)
        reinterpret_cast<float4*>(op)[q] =
            make_float4(acc[q * 4 + 0] * inv, acc[q * 4 + 1] * inv,
                        acc[q * 4 + 2] * inv, acc[q * 4 + 3] * inv);
}

// ---------------------------------------------------------------------------
extern "C" void kernel_launch(void* const* d_in, const int* in_sizes, int n_in,
                              void* d_out, int out_size) {
    const float* x   = (const float*)d_in[0];
    const int*   src = (const int*)  d_in[1];
    const int*   dst = (const int*)  d_in[2];
    const float* Wl  = (const float*)d_in[3];
    const float* bl  = (const float*)d_in[4];
    const float* Wa  = (const float*)d_in[5];
    const float* ba  = (const float*)d_in[6];
    const float* Wd  = (const float*)d_in[7];
    const float* bd  = (const float*)d_in[8];
    const float* Wf  = (const float*)d_in[9];
    const float* bf  = (const float*)d_in[10];
    float* out = (float*)d_out;

    int N = in_sizes[0] / DIN;
    int E = in_sizes[1];
    int NB = (N + SCAN_B - 1) / SCAN_B;

    static cudaStream_t s_side = nullptr;
    static cudaEvent_t  ev_fork = nullptr, ev_join = nullptr;
    static int* p_degfv = nullptr;
    if (s_side == nullptr) {
        cudaStreamCreateWithFlags(&s_side, cudaStreamNonBlocking);
        cudaEventCreateWithFlags(&ev_fork, cudaEventDisableTiming);
        cudaEventCreateWithFlags(&ev_join, cudaEventDisableTiming);
        cudaGetSymbolAddress((void**)&p_degfv, g_degfv);
    }

    cudaEventRecord(ev_fork, 0);
    cudaStreamWaitEvent(s_side, ev_fork, 0);

    cudaMemsetAsync(p_degfv, 0, (size_t)(N + NB) * sizeof(int), s_side);
    {
        int qthreads = (E + 3) / 4;
        hist_kernel<<<(qthreads + 255) / 256, 256, 0, s_side>>>(dst, E);
    }
    scan_onepass_kernel<<<NB, SCAN_B, 0, s_side>>>(N, NB);
    {
        int qthreads = (E + 3) / 4;
        scatter_kernel<<<(qthreads + 255) / 256, 256, 0, s_side>>>(src, dst, E);
    }
    cudaEventRecord(ev_join, s_side);

    precompute_kernel<<<1, 512>>>(Wl, bl, Wa, ba, Wd, bd, Wf, bf);
    node_kernel<<<(N + 127) / 128, 128>>>(x, N);

    cudaStreamWaitEvent(0, ev_join, 0);
    long long threads = (long long)N * 4;
    int blocks = (int)((threads + 255) / 256);
    reduce_kernel<<<blocks, 256>>>(out, N);
}

// round 16
// speedup vs baseline: 1.0989x; 1.0989x over previous
#include <cuda_runtime.h>
#include <cuda_fp16.h>

#define NMAX   100000
#define EMAX   1600000
#define DIN    64
#define NHEAD  4
#define HDIM   16
#define FEAT   64   // NHEAD*HDIM
#define ROW    80   // augmented width: 64 h | u | v+off | as0..3 | ad0..3(+ba) | 6 pad
#define SCAN_B 1024

// -------- scratch (static device globals; no allocations allowed) ----------
__device__ __align__(16) static __half g_h[(size_t)NMAX * FEAT];
__device__ __align__(16) static float2 g_uas[NMAX * NHEAD];  // (u, as_head)
__device__ __align__(16) static float2 g_vad[NMAX * NHEAD];  // (v+off, ad_head+ba)

__device__ __align__(16) static float g_Wp[DIN * ROW];  // augmented weights
__device__ __align__(16) static float g_bp[ROW];        // augmented bias

__device__ static int g_degfv[NMAX + 256];   // deg + scan publish flags
__device__ static int g_cursor[NMAX];
__device__ static int g_offs[NMAX + 1];
__device__ static int g_srcs[EMAX];

// ---------------------------------------------------------------------------
// 1) Build W' (64x80) + b'(80) IN PARALLEL: one block per weight row j,
//    one thread per output column c. Column layout:
//    c<64: Wl[j][c]; 64: cu; 65: cv; 66+h: Wl_head@Wa_s; 70+h: Wl_head@Wa_d.
//    bias: c<64: bl; 65: off; 66+h: bl.Wa_s; 70+h: bl.Wa_d + ba; else 0.
// ---------------------------------------------------------------------------
__global__ void __launch_bounds__(80)
precompute_kernel(const float* __restrict__ Wl, const float* __restrict__ bl,
                  const float* __restrict__ Wa, const float* __restrict__ ba,
                  const float* __restrict__ Wd, const float* __restrict__ bd,
                  const float* __restrict__ Wf, const float* __restrict__ bf) {
    __shared__ float wfu[DIN], wfv[DIN], s_wa[2 * HDIM];
    int j = blockIdx.x;      // 0..63
    int c = threadIdx.x;     // 0..79
    if (c < DIN) {
        float f0 = Wf[c], f1 = Wf[DIN + c], f2 = Wf[2 * DIN + c];
        wfu[c] = f0 + f2;
        wfv[c] = f1 - f2;
    }
    if (c < 2 * HDIM) s_wa[c] = Wa[c];
    __syncthreads();

    const float* wlrow = Wl + j * DIN;
    float w = 0.f;
    if (c < 64) {
        w = wlrow[c];
    } else if (c == 64) {
        const float* wd = Wd + j * DIN;
#pragma unroll 8
        for (int k = 0; k < DIN; k++) w += wd[k] * wfu[k];
    } else if (c == 65) {
        const float* wd = Wd + j * DIN;
#pragma unroll 8
        for (int k = 0; k < DIN; k++) w += wd[k] * wfv[k];
    } else if (c < 70) {
        int h = c - 66;
#pragma unroll
        for (int k = 0; k < HDIM; k++) w += wlrow[h * HDIM + k] * s_wa[k];
    } else if (c < 74) {
        int h = c - 70;
#pragma unroll
        for (int k = 0; k < HDIM; k++) w += wlrow[h * HDIM + k] * s_wa[HDIM + k];
    }
    g_Wp[j * ROW + c] = w;

    if (j == 0) {
        float b = 0.f;
        if (c < 64) {
            b = bl[c];
        } else if (c == 65) {
            b = bf[0];
            for (int k = 0; k < DIN; k++) b += bd[k] * (wfu[k] + wfv[k]);
        } else if (c >= 66 && c < 70) {
            int h = c - 66;
#pragma unroll
            for (int k = 0; k < HDIM; k++) b += bl[h * HDIM + k] * s_wa[k];
        } else if (c >= 70 && c < 74) {
            int h = c - 70;
#pragma unroll
            for (int k = 0; k < HDIM; k++) b += bl[h * HDIM + k] * s_wa[HDIM + k];
            b += ba[0];
        }
        g_bp[c] = b;
    }
}

// ---------------------------------------------------------------------------
// 2) Degree histogram over dst, 4 edges/thread (deg zeroed by memsetAsync).
// ---------------------------------------------------------------------------
__global__ void hist_kernel(const int* __restrict__ dst, int E) {
    int q = blockIdx.x * blockDim.x + threadIdx.x;
    int e = q * 4;
    if (e + 3 < E) {
        int4 d4 = *reinterpret_cast<const int4*>(dst + e);
        atomicAdd(&g_degfv[d4.x], 1);
        atomicAdd(&g_degfv[d4.y], 1);
        atomicAdd(&g_degfv[d4.z], 1);
        atomicAdd(&g_degfv[d4.w], 1);
    } else {
        for (int k = e; k < E; k++) atomicAdd(&g_degfv[dst[k]], 1);
    }
}

// ---------------------------------------------------------------------------
// 3) Single-pass exclusive scan (98 co-resident blocks, aggregate lookback).
// ---------------------------------------------------------------------------
__global__ void scan_onepass_kernel(int N, int NB) {
    __shared__ int sm[SCAN_B];
    __shared__ int s_base;
    int b = blockIdx.x;
    int tid = threadIdx.x;
    int idx = b * SCAN_B + tid;

    int v = (idx < N) ? g_degfv[idx] : 0;
    sm[tid] = v;
    __syncthreads();
#pragma unroll
    for (int o = 1; o < SCAN_B; o <<= 1) {
        int tmp = (tid >= o) ? sm[tid - o] : 0;
        __syncthreads();
        sm[tid] += tmp;
        __syncthreads();
    }
    int incl = sm[tid];
    int agg = sm[SCAN_B - 1];

    if (tid == 0) {
        __threadfence();
        atomicExch(&g_degfv[NMAX + b], agg + 1);
    }
    if (tid < 32) {
        int contrib = 0;
        for (int t = tid; t < b; t += 32) {
            int fv;
            do { fv = atomicAdd(&g_degfv[NMAX + t], 0); } while (fv == 0);
            contrib += fv - 1;
        }
#pragma unroll
        for (int o = 16; o > 0; o >>= 1)
            contrib += __shfl_down_sync(0xffffffffu, contrib, o);
        if (tid == 0) s_base = contrib;
    }
    __syncthreads();
    int base = s_base;

    if (idx < N) {
        int off = base + incl - v;
        g_offs[idx] = off;
        g_cursor[idx] = off;
    }
    if (b == NB - 1 && tid == 0) g_offs[N] = base + agg;
}

// ---------------------------------------------------------------------------
// 4) Scatter src ids into dst-sorted order, 4 edges/thread.
// ---------------------------------------------------------------------------
__global__ void scatter_kernel(const int* __restrict__ src,
                               const int* __restrict__ dst, int E) {
    int q = blockIdx.x * blockDim.x + threadIdx.x;
    int e = q * 4;
    if (e + 3 < E) {
        int4 s4 = *reinterpret_cast<const int4*>(src + e);
        int4 d4 = *reinterpret_cast<const int4*>(dst + e);
        g_srcs[atomicAdd(&g_cursor[d4.x], 1)] = s4.x;
        g_srcs[atomicAdd(&g_cursor[d4.y], 1)] = s4.y;
        g_srcs[atomicAdd(&g_cursor[d4.z], 1)] = s4.z;
        g_srcs[atomicAdd(&g_cursor[d4.w], 1)] = s4.w;
    } else {
        for (int k = e; k < E; k++)
            g_srcs[atomicAdd(&g_cursor[dst[k]], 1)] = src[k];
    }
}

// ---------------------------------------------------------------------------
// 5) Node GEMM: x[N,64] @ W'[64,80]. 8-thread groups own 8 nodes; thread c
//    computes 10 columns for all 8 nodes. LDS/node = 2.5 KB, ~420 instr/node.
// ---------------------------------------------------------------------------
__global__ void __launch_bounds__(128)
node_kernel(const float* __restrict__ x, int N) {
    __shared__ __align__(16) float s_wp[DIN * ROW];   // 20480 B
    __shared__ __align__(16) float s_bp[ROW];

    int tid = threadIdx.x;
    {
        const float4* src4 = reinterpret_cast<const float4*>(g_Wp);
        float4* dst4 = reinterpret_cast<float4*>(s_wp);
        for (int i = tid; i < DIN * ROW / 4; i += 128) dst4[i] = src4[i];
        if (tid < ROW) s_bp[tid] = g_bp[tid];
    }
    __syncthreads();

    int grp = tid >> 3;          // 0..15
    int c = tid & 7;             // col chunk: [c*10, c*10+10)
    int nbase = blockIdx.x * 128 + grp * 8;
    if (nbase >= N) return;

    // 8 nodes x 5 f32x2 accumulators, bias-seeded
    unsigned long long acc[8][5];
    {
        const unsigned long long* bp =
            reinterpret_cast<const unsigned long long*>(&s_bp[c * 10]);
#pragma unroll
        for (int q = 0; q < 5; q++) {
            unsigned long long b = bp[q];
#pragma unroll
            for (int m = 0; m < 8; m++) acc[m][q] = b;
        }
    }

    const float4* xr[8];
#pragma unroll
    for (int m = 0; m < 8; m++) {
        int nm = min(nbase + m, N - 1);
        xr[m] = reinterpret_cast<const float4*>(x + (size_t)nm * DIN);
    }

#pragma unroll 1
    for (int i4 = 0; i4 < DIN / 4; i4++) {
        float4 xv[8];
#pragma unroll
        for (int m = 0; m < 8; m++) xv[m] = xr[m][i4];
#pragma unroll
        for (int j = 0; j < 4; j++) {
            int i = i4 * 4 + j;
            unsigned long long xs[8];
#pragma unroll
            for (int m = 0; m < 8; m++) {
                float xi = (j == 0) ? xv[m].x : (j == 1) ? xv[m].y
                         : (j == 2) ? xv[m].z : xv[m].w;
                asm("mov.b64 %0, {%1, %1};" : "=l"(xs[m]) : "f"(xi));
            }
            const unsigned long long* wrow =
                reinterpret_cast<const unsigned long long*>(&s_wp[i * ROW + c * 10]);
#pragma unroll
            for (int q = 0; q < 5; q++) {
                unsigned long long wv = wrow[q];
#pragma unroll
                for (int m = 0; m < 8; m++)
                    asm("fma.rn.f32x2 %0, %1, %2, %0;"
                        : "+l"(acc[m][q]) : "l"(wv), "l"(xs[m]));
            }
        }
    }

    // Writeback. Col map: t0..t5 = h[0..59]; t6 = h[60..63], u, v+off, as0..3;
    // t7 = ad0..3(+ba), pads. One shfl moves v+off from lane6 to lane7.
    int lane6 = (tid & ~7) | 6;
#pragma unroll
    for (int m = 0; m < 8; m++) {
        int n = nbase + m;
        float val[10];
#pragma unroll
        for (int q = 0; q < 5; q++)
            asm("mov.b64 {%0, %1}, %2;"
                : "=f"(val[2 * q]), "=f"(val[2 * q + 1]) : "l"(acc[m][q]));

        float vbrd = __shfl_sync(0xffffffffu, val[5], lane6);

        if (n < N) {
            if (c < 6) {
                __half2* hp = reinterpret_cast<__half2*>(&g_h[(size_t)n * FEAT + c * 10]);
#pragma unroll
                for (int q = 0; q < 5; q++)
                    hp[q] = __floats2half2_rn(val[2 * q], val[2 * q + 1]);
            } else if (c == 6) {
                __half2* hp = reinterpret_cast<__half2*>(&g_h[(size_t)n * FEAT + 60]);
                hp[0] = __floats2half2_rn(val[0], val[1]);
                hp[1] = __floats2half2_rn(val[2], val[3]);
                float u = val[4];
#pragma unroll
                for (int h = 0; h < NHEAD; h++)
                    g_uas[n * NHEAD + h] = make_float2(u, val[6 + h]);
            } else if (c == 7) {
#pragma unroll
                for (int h = 0; h < NHEAD; h++)
                    g_vad[n * NHEAD + h] = make_float2(vbrd, val[h]);
            }
        }
    }
}

// ---------------------------------------------------------------------------
// 6) CSR reduce: 4 threads per dst node (lane == head, 16 fp16 features).
// ---------------------------------------------------------------------------
__global__ void __launch_bounds__(256)
reduce_kernel(float* __restrict__ out, int N) {
    int gid = blockIdx.x * blockDim.x + threadIdx.x;
    int n = gid >> 2;
    if (n >= N) return;
    int head = gid & 3;

    int beg = g_offs[n];
    int end = g_offs[n + 1];

    float2 vad = __ldg(&g_vad[n * NHEAD + head]);
    float vofs = vad.x;
    float adb  = vad.y;

    float acc[16];
#pragma unroll
    for (int k = 0; k < 16; k++) acc[k] = 0.f;
    float dsum = 0.f;

    if (beg < end) {
        int s = __ldg(&g_srcs[beg]);
        for (int p = beg; p < end; p++) {
            int s_next = (p + 1 < end) ? __ldg(&g_srcs[p + 1]) : 0;
            float2 ua = __ldg(&g_uas[s * NHEAD + head]);
            const uint4* hp = reinterpret_cast<const uint4*>(
                &g_h[(size_t)s * FEAT + head * HDIM]);
            uint4 raw0 = hp[0];
            uint4 raw1 = hp[1];

            float arg = ua.x + vofs;
            float sg = (arg > 0.f) ? 1.f : ((arg < 0.f) ? -1.f : 0.f);
            float al = sg * ua.y + adb;
            al = (al > 0.f) ? al : 0.01f * al;          // leaky_relu
            float w = __expf(al);
            float ws = w * sg;

            const __half2* c0 = reinterpret_cast<const __half2*>(&raw0);
            const __half2* c1 = reinterpret_cast<const __half2*>(&raw1);
#pragma unroll
            for (int q = 0; q < 4; q++) {
                float2 f0 = __half22float2(c0[q]);
                float2 f1 = __half22float2(c1[q]);
                acc[q * 2 + 0] += ws * f0.x;
                acc[q * 2 + 1] += ws * f0.y;
                acc[8 + q * 2 + 0] += ws * f1.x;
                acc[8 + q * 2 + 1] += ws * f1.y;
            }
            dsum += w;
            s = s_next;
        }
    }

    float inv = 1.f / fmaxf(dsum, 1e-16f);
    float* op = &out[(size_t)n * FEAT + head * HDIM];
#pragma unroll
    for (int q = 0; q < 4; q++)
        reinterpret_cast<float4*>(op)[q] =
            make_float4(acc[q * 4 + 0] * inv, acc[q * 4 + 1] * inv,
                        acc[q * 4 + 2] * inv, acc[q * 4 + 3] * inv);
}

// ---------------------------------------------------------------------------
extern "C" void kernel_launch(void* const* d_in, const int* in_sizes, int n_in,
                              void* d_out, int out_size) {
    const float* x   = (const float*)d_in[0];
    const int*   src = (const int*)  d_in[1];
    const int*   dst = (const int*)  d_in[2];
    const float* Wl  = (const float*)d_in[3];
    const float* bl  = (const float*)d_in[4];
    const float* Wa  = (const float*)d_in[5];
    const float* ba  = (const float*)d_in[6];
    const float* Wd  = (const float*)d_in[7];
    const float* bd  = (const float*)d_in[8];
    const float* Wf  = (const float*)d_in[9];
    const float* bf  = (const float*)d_in[10];
    float* out = (float*)d_out;

    int N = in_sizes[0] / DIN;
    int E = in_sizes[1];
    int NB = (N + SCAN_B - 1) / SCAN_B;

    static cudaStream_t s_side = nullptr;
    static cudaEvent_t  ev_fork = nullptr, ev_join = nullptr;
    static int* p_degfv = nullptr;
    if (s_side == nullptr) {
        cudaStreamCreateWithFlags(&s_side, cudaStreamNonBlocking);
        cudaEventCreateWithFlags(&ev_fork, cudaEventDisableTiming);
        cudaEventCreateWithFlags(&ev_join, cudaEventDisableTiming);
        cudaGetSymbolAddress((void**)&p_degfv, g_degfv);
    }

    cudaEventRecord(ev_fork, 0);
    cudaStreamWaitEvent(s_side, ev_fork, 0);

    cudaMemsetAsync(p_degfv, 0, (size_t)(N + NB) * sizeof(int), s_side);
    {
        int qthreads = (E + 3) / 4;
        hist_kernel<<<(qthreads + 255) / 256, 256, 0, s_side>>>(dst, E);
    }
    scan_onepass_kernel<<<NB, SCAN_B, 0, s_side>>>(N, NB);
    {
        int qthreads = (E + 3) / 4;
        scatter_kernel<<<(qthreads + 255) / 256, 256, 0, s_side>>>(src, dst, E);
    }
    cudaEventRecord(ev_join, s_side);

    precompute_kernel<<<64, 80>>>(Wl, bl, Wa, ba, Wd, bd, Wf, bf);
    node_kernel<<<(N + 127) / 128, 128>>>(x, N);

    cudaStreamWaitEvent(0, ev_join, 0);
    long long threads = (long long)N * 4;
    int blocks = (int)((threads + 255) / 256);
    reduce_kernel<<<blocks, 256>>>(out, N);
}